// round 10
// baseline (speedup 1.0000x reference)
#include <cuda_runtime.h>
#include <cstdint>
#include <math.h>

// ---------------------------------------------------------------------------
// LOUPE sampler, single fused kernel.
//  Host: threefry split-chain (data-independent) -> 32 candidate sub-keys.
//  Blocks 0-31: one rejection-sampling candidate each; last (ticket) selects
//    the first accepted candidate, emits d_mask, releases d_flag.
//  ALL blocks: spin on d_flag, then apply their slice (load-skip on zero
//    lines). Last finishing block resets flag/ticket/done for graph replay.
// Output: [masked_kspace 256*2*320*320 f32][mask_full 256*1*320*320 f32]
// ---------------------------------------------------------------------------

#define SLOPE  5.0f
#define LN     320
#define NPROBE 32
#define TPB    256

struct SubKeys {
    uint2 s[NPROBE];   // sub-key for candidate i
    uint2 tail;        // key state after NPROBE splits (fallback chain)
};

__device__ float         d_mask[LN];
__device__ int           d_cnt[NPROBE];
__device__ uint32_t      d_words[NPROBE][10];
__device__ int           d_ticket = 0;
__device__ volatile int  d_flag   = 0;
__device__ int           d_done   = 0;

// --- threefry2x32, 20 rounds (JAX), host+device ---
__host__ __device__ __forceinline__ uint32_t rotl32(uint32_t v, int d) {
    return (v << d) | (v >> (32 - d));
}

__host__ __device__ __forceinline__ void threefry2x32(
    uint32_t k0, uint32_t k1, uint32_t c0, uint32_t c1,
    uint32_t& o0, uint32_t& o1) {
    uint32_t k2 = k0 ^ k1 ^ 0x1BD11BDAu;
    uint32_t x0 = c0 + k0;
    uint32_t x1 = c1 + k1;
#define TF_ROUND(r) { x0 += x1; x1 = rotl32(x1, (r)); x1 ^= x0; }
    TF_ROUND(13) TF_ROUND(15) TF_ROUND(26) TF_ROUND(6)
    x0 += k1; x1 += k2 + 1u;
    TF_ROUND(17) TF_ROUND(29) TF_ROUND(16) TF_ROUND(24)
    x0 += k2; x1 += k0 + 2u;
    TF_ROUND(13) TF_ROUND(15) TF_ROUND(26) TF_ROUND(6)
    x0 += k0; x1 += k1 + 3u;
    TF_ROUND(17) TF_ROUND(29) TF_ROUND(16) TF_ROUND(24)
    x0 += k1; x1 += k2 + 4u;
    TF_ROUND(13) TF_ROUND(15) TF_ROUND(26) TF_ROUND(6)
    x0 += k2; x1 += k0 + 5u;
#undef TF_ROUND
    o0 = x0; o1 = x1;
}

__device__ __forceinline__ float bits_to_uniform(uint32_t b) {
    return __uint_as_float((b >> 9) | 0x3f800000u) - 1.0f;
}

// ---------------------------------------------------------------------------
__global__ void __launch_bounds__(TPB) fused_kernel(
    const float* __restrict__ logits, const float* __restrict__ sparsity_p,
    SubKeys subs,
    const float4* __restrict__ ksp, float4* __restrict__ out,
    int n4m, int n4tot) {
    const int tid  = threadIdx.x;
    const int wid  = tid >> 5;
    const int lane = tid & 31;
    const int b    = blockIdx.x;

    // ==================== mask phase (blocks 0..NPROBE-1) ====================
    if (b < NPROBE) {
        __shared__ float    xs[LN];
        __shared__ float    wsum[8];
        __shared__ float    sh_xbar;
        __shared__ uint32_t wl[10];
        __shared__ int      sh_last, sh_sel;

        // 256 threads cover 320 lines: j1 = tid, j2 = 256+tid (tid<64)
        float s1 = 1.0f / (1.0f + expf(-SLOPE * logits[tid]));
        float s2 = 0.0f;
        if (tid < 64) s2 = 1.0f / (1.0f + expf(-SLOPE * logits[256 + tid]));

        // block reduce: xbar
        float a = s1 + s2;
        for (int o = 16; o > 0; o >>= 1) a += __shfl_down_sync(0xffffffffu, a, o);
        if (lane == 0) wsum[wid] = a;
        __syncthreads();
        if (wid == 0) {
            float t = (lane < 8) ? wsum[lane] : 0.0f;
            for (int o = 4; o > 0; o >>= 1) t += __shfl_down_sync(0xffffffffu, t, o);
            if (lane == 0) sh_xbar = t / (float)LN;
        }
        __syncthreads();

        // rescale; mean(rescaled) == sparsity analytically (3x tolerance margin)
        const float sparsity = __ldg(sparsity_p);
        const float xbar = sh_xbar;
        const float r    = sparsity / xbar;
        const float beta = (1.0f - sparsity) / (1.0f - xbar);
        const bool  le   = (r <= 1.0f);
        float x1 = le ? (s1 * r) : (1.0f - (1.0f - s1) * beta);
        float x2 = le ? (s2 * r) : (1.0f - (1.0f - s2) * beta);
        xs[tid] = x1;
        if (tid < 64) xs[256 + tid] = x2;
        const float xm  = sparsity;
        const float tol = 1e-3f + 1e-5f * fabsf(xm);

        // draw candidate b: bits(key,j) = x0^x1 of TF(key, 0, j)
        const uint2 sub = subs.s[b];
        uint32_t u, v;
        threefry2x32(sub.x, sub.y, 0u, (uint32_t)tid, u, v);
        const bool pred1 = x1 > bits_to_uniform(u ^ v);
        bool pred2 = false;
        if (tid < 64) {
            uint32_t u2, v2;
            threefry2x32(sub.x, sub.y, 0u, (uint32_t)(256 + tid), u2, v2);
            pred2 = x2 > bits_to_uniform(u2 ^ v2);
        }

        uint32_t b1 = __ballot_sync(0xffffffffu, pred1);
        if (lane == 0) wl[wid] = b1;
        uint32_t b2 = __ballot_sync(0xffffffffu, pred2);
        if (wid < 2 && lane == 0) wl[8 + wid] = b2;
        __syncthreads();

        if (tid < 10) d_words[b][tid] = wl[tid];
        if (tid == 0) {
            int c = 0;
            #pragma unroll
            for (int i = 0; i < 10; i++) c += __popc(wl[i]);
            d_cnt[b] = c;
            __threadfence();                       // publish words/cnt
            int t = atomicAdd(&d_ticket, 1);
            sh_last = (t == NPROBE - 1) ? 1 : 0;
            if (sh_last) d_ticket = 0;             // reset for next replay
        }
        __syncthreads();

        if (sh_last) {
            // selection
            if (tid == 0) {
                int sel = -1;
                for (int i = 0; i < NPROBE; i++) {
                    float m = (float)(*(volatile int*)&d_cnt[i]) / (float)LN;
                    if (fabsf(m - xm) <= tol) { sel = i; break; }
                }
                sh_sel = sel;
            }
            __syncthreads();
            const int sel = sh_sel;

            float v1, v2 = 0.0f;
            if (sel >= 0) {
                uint32_t w1 = *(volatile uint32_t*)&d_words[sel][tid >> 5];
                v1 = ((w1 >> lane) & 1u) ? 1.0f : 0.0f;
                if (tid < 64) {
                    uint32_t w2 = *(volatile uint32_t*)&d_words[sel][8 + (tid >> 5)];
                    v2 = ((w2 >> lane) & 1u) ? 1.0f : 0.0f;
                }
            } else {
                // fallback (rare): continue sequential split chain
                __shared__ uint32_t key0, key1, sub0, sub1;
                if (tid == 0) { key0 = subs.tail.x; key1 = subs.tail.y; }
                __syncthreads();
                bool r1 = false, r2 = false;
                for (int iter = 0; iter < 100000; ++iter) {
                    if (tid == 0) {   // split: new=TF(k,0,0), sub=TF(k,0,1)
                        uint32_t nk0, nk1, ns0, ns1;
                        threefry2x32(key0, key1, 0u, 0u, nk0, nk1);
                        threefry2x32(key0, key1, 0u, 1u, ns0, ns1);
                        key0 = nk0; key1 = nk1;
                        sub0 = ns0; sub1 = ns1;
                    }
                    __syncthreads();
                    uint32_t uu, vv;
                    threefry2x32(sub0, sub1, 0u, (uint32_t)tid, uu, vv);
                    r1 = xs[tid] > bits_to_uniform(uu ^ vv);
                    r2 = false;
                    if (tid < 64) {
                        uint32_t uu2, vv2;
                        threefry2x32(sub0, sub1, 0u, (uint32_t)(256 + tid), uu2, vv2);
                        r2 = xs[256 + tid] > bits_to_uniform(uu2 ^ vv2);
                    }
                    int c = __syncthreads_count(r1 ? 1 : 0)
                          + __syncthreads_count(r2 ? 1 : 0);
                    float m = (float)c / (float)LN;
                    if (fabsf(m - xm) <= tol) break;
                }
                v1 = r1 ? 1.0f : 0.0f;
                v2 = r2 ? 1.0f : 0.0f;
            }
            if (tid == 0) v1 = 1.0f;                 // preselect line 0
            if (tid == 63) v2 = 1.0f;                // preselect line 319
            d_mask[tid] = v1;
            if (tid < 64) d_mask[256 + tid] = v2;
            __threadfence();                          // release
            d_flag = 1;
        }
    }

    // ==================== apply phase (ALL blocks) ====================
    if (tid == 0) {
        while (d_flag == 0) __nanosleep(64);
    }
    __syncthreads();

    __shared__ float smask[8];
    const int base = b * TPB;

    // stage the <=5 mask rows this block touches (volatile -> L2-coherent)
    int r0 = -1, nr = 0;
    if (base + TPB <= n4m) {                 // fully in masked_kspace region
        r0 = base / 80;
        nr = (base + TPB - 1) / 80 - r0 + 1;
    } else if (base >= n4m) {                // fully in mask_full region
        r0 = (base - n4m) / 80;
        nr = (base + TPB - 1 - n4m) / 80 - r0 + 1;
    }
    if (r0 >= 0 && tid < nr)
        smask[tid] = *(volatile float*)&d_mask[(r0 + tid) % LN];
    __syncthreads();

    const int idx = base + tid;
    if (idx < n4tot) {
        if (idx < n4m) {
            int row = idx / 80;              // W=320 -> 80 float4 per row
            float m = (r0 >= 0) ? smask[row - r0]
                                : *(volatile float*)&d_mask[row % LN];
            if (m != 0.0f) {
                __stcs(&out[idx], __ldcs(&ksp[idx]));
            } else {
                __stcs(&out[idx], make_float4(0.f, 0.f, 0.f, 0.f));
            }
        } else {
            int row = (idx - n4m) / 80;
            float m = (r0 >= 0) ? smask[row - r0]
                                : *(volatile float*)&d_mask[row % LN];
            __stcs(&out[idx], make_float4(m, m, m, m));
        }
    }

    // reset control state for next graph replay (last finishing block)
    if (tid == 0) {
        int t = atomicAdd(&d_done, 1);
        if (t == (int)gridDim.x - 1) {
            d_done = 0;
            d_flag = 0;
        }
    }
}

extern "C" void kernel_launch(void* const* d_in, const int* in_sizes, int n_in,
                              void* d_out, int out_size) {
    const float* kspace   = (const float*)d_in[0];  // (256,2,320,320)
    const float* sparsity = (const float*)d_in[1];  // scalar
    const float* logits   = (const float*)d_in[2];  // (320,)

    // Host-side threefry split chain (independent of device inputs).
    // JAX partitionable split: new_key = TF(key,0,0), sub = TF(key,0,1).
    SubKeys subs;
    {
        uint32_t k0 = 0u, k1 = 42u;   // jax.random.key(42)
        for (int i = 0; i < NPROBE; i++) {
            uint32_t s0, s1, n0, n1;
            threefry2x32(k0, k1, 0u, 1u, s0, s1);
            threefry2x32(k0, k1, 0u, 0u, n0, n1);
            subs.s[i] = make_uint2(s0, s1);
            k0 = n0; k1 = n1;
        }
        subs.tail = make_uint2(k0, k1);
    }

    int n4m   = in_sizes[0] / 4;
    int n4tot = out_size / 4;
    int blocks = (n4tot + TPB - 1) / TPB;
    fused_kernel<<<blocks, TPB>>>(logits, sparsity, subs,
                                  (const float4*)kspace, (float4*)d_out,
                                  n4m, n4tot);
}

// round 11
// speedup vs baseline: 1.4464x; 1.4464x over previous
#include <cuda_runtime.h>
#include <cstdint>
#include <math.h>

// ---------------------------------------------------------------------------
// LOUPE sampler.
//  Host: threefry split-chain (data-independent) -> 32 candidate sub-keys.
//  mask_kernel : ONE block x 1024 threads. Warps 0-9: sigmoid + xbar reduce;
//    all 32 warps: one rejection-sampling candidate each (smem only);
//    in-block selection -> d_mask. xm == sparsity analytically (validated).
//  apply_mask  : bandwidth kernel (at LTS ceiling); load-skip on zero lines.
// Output: [masked_kspace 256*2*320*320 f32][mask_full 256*1*320*320 f32]
// ---------------------------------------------------------------------------

#define SLOPE  5.0f
#define LN     320
#define NPROBE 32

struct SubKeys {
    uint2 s[NPROBE];   // sub-key for candidate i
    uint2 tail;        // key state after NPROBE splits (fallback chain)
};

__device__ float d_mask[LN];

// --- threefry2x32, 20 rounds (JAX), host+device ---
__host__ __device__ __forceinline__ uint32_t rotl32(uint32_t v, int d) {
    return (v << d) | (v >> (32 - d));
}

__host__ __device__ __forceinline__ void threefry2x32(
    uint32_t k0, uint32_t k1, uint32_t c0, uint32_t c1,
    uint32_t& o0, uint32_t& o1) {
    uint32_t k2 = k0 ^ k1 ^ 0x1BD11BDAu;
    uint32_t x0 = c0 + k0;
    uint32_t x1 = c1 + k1;
#define TF_ROUND(r) { x0 += x1; x1 = rotl32(x1, (r)); x1 ^= x0; }
    TF_ROUND(13) TF_ROUND(15) TF_ROUND(26) TF_ROUND(6)
    x0 += k1; x1 += k2 + 1u;
    TF_ROUND(17) TF_ROUND(29) TF_ROUND(16) TF_ROUND(24)
    x0 += k2; x1 += k0 + 2u;
    TF_ROUND(13) TF_ROUND(15) TF_ROUND(26) TF_ROUND(6)
    x0 += k0; x1 += k1 + 3u;
    TF_ROUND(17) TF_ROUND(29) TF_ROUND(16) TF_ROUND(24)
    x0 += k1; x1 += k2 + 4u;
    TF_ROUND(13) TF_ROUND(15) TF_ROUND(26) TF_ROUND(6)
    x0 += k2; x1 += k0 + 5u;
#undef TF_ROUND
    o0 = x0; o1 = x1;
}

__device__ __forceinline__ float bits_to_uniform(uint32_t b) {
    return __uint_as_float((b >> 9) | 0x3f800000u) - 1.0f;
}

// ---------------------------------------------------------------------------
// mask_kernel: 1 block x 1024 threads (32 warps).
//   warps 0-9 : sigmoid(lines) + xbar reduction + rescale into smem
//   warp  w   : candidate w: 10 threefry/lane over all 320 lines, ballot+popc
//   in-block  : select first accepted candidate, emit d_mask
// JAX partitionable threefry: bits(key,j) = x0^x1 of TF(key, 0, j).
// mean(rescaled) == sparsity analytically (r<=1: r*xbar = s; else symmetric);
// acceptance margin is 3x the float noise (validated R10, rel_err 0.0).
// ---------------------------------------------------------------------------
__global__ void __launch_bounds__(1024) mask_kernel(
    const float* __restrict__ logits, const float* __restrict__ sparsity_p,
    SubKeys subs) {
    __shared__ float    xs[LN];
    __shared__ float    wsum[10];
    __shared__ float    sh_xbar;
    __shared__ uint32_t words[NPROBE][10];
    __shared__ int      cnt[NPROBE];
    __shared__ int      sh_sel;

    const int tid  = threadIdx.x;
    const int wid  = tid >> 5;
    const int lane = tid & 31;

    const float sparsity = __ldg(sparsity_p);   // issue early

    // --- sigmoid + xbar (warps 0-9 cover the 320 lines) ---
    float s = 0.0f;
    if (tid < LN) s = 1.0f / (1.0f + expf(-SLOPE * logits[tid]));
    if (wid < 10) {
        float a = s;
        for (int o = 16; o > 0; o >>= 1) a += __shfl_down_sync(0xffffffffu, a, o);
        if (lane == 0) wsum[wid] = a;
    }
    __syncthreads();
    if (wid == 0) {
        float t = (lane < 10) ? wsum[lane] : 0.0f;
        for (int o = 8; o > 0; o >>= 1) t += __shfl_down_sync(0xffffffffu, t, o);
        if (lane == 0) sh_xbar = t / (float)LN;
    }
    __syncthreads();

    // --- rescale into smem ---
    const float xbar = sh_xbar;
    const float r    = sparsity / xbar;
    const float beta = (1.0f - sparsity) / (1.0f - xbar);
    if (tid < LN)
        xs[tid] = (r <= 1.0f) ? (s * r) : (1.0f - (1.0f - s) * beta);
    __syncthreads();

    const float xm  = sparsity;                 // analytic mean of rescaled map
    const float tol = 1e-3f + 1e-5f * fabsf(xm);

    // --- draw phase: warp w evaluates candidate w (all in smem/registers) ---
    {
        const uint2 sub = subs.s[wid];
        int c = 0;
        #pragma unroll
        for (int k = 0; k < 10; k++) {
            const int j = k * 32 + lane;
            uint32_t u, v;
            threefry2x32(sub.x, sub.y, 0u, (uint32_t)j, u, v);
            const int pred = xs[j] > bits_to_uniform(u ^ v);
            const uint32_t b = __ballot_sync(0xffffffffu, pred);
            if (lane == k) words[wid][k] = b;
            c += __popc(b);
        }
        if (lane == 0) cnt[wid] = c;
    }
    __syncthreads();

    // --- selection ---
    if (tid == 0) {
        int sel = -1;
        for (int i = 0; i < NPROBE; i++) {
            float m = (float)cnt[i] / (float)LN;
            if (fabsf(m - xm) <= tol) { sel = i; break; }
        }
        sh_sel = sel;
    }
    __syncthreads();
    const int sel = sh_sel;

    if (sel >= 0) {
        if (tid < LN) {
            uint32_t w = words[sel][tid >> 5];
            float v = ((w >> lane) & 1u) ? 1.0f : 0.0f;
            if (tid == 0 || tid == LN - 1) v = 1.0f;
            d_mask[tid] = v;
        }
        return;
    }

    // --- fallback (rare): continue sequential split chain from subs.tail ---
    __shared__ uint32_t key0, key1, sub0, sub1;
    if (tid == 0) { key0 = subs.tail.x; key1 = subs.tail.y; }
    __syncthreads();
    const float x = (tid < LN) ? xs[tid] : 0.0f;
    bool res = false;
    for (int iter = 0; iter < 100000; ++iter) {
        if (tid == 0) {   // split(key): new=TF(key,0,0), sub=TF(key,0,1)
            uint32_t nk0, nk1, ns0, ns1;
            threefry2x32(key0, key1, 0u, 0u, nk0, nk1);
            threefry2x32(key0, key1, 0u, 1u, ns0, ns1);
            key0 = nk0; key1 = nk1;
            sub0 = ns0; sub1 = ns1;
        }
        __syncthreads();
        bool rr = false;
        if (tid < LN) {
            uint32_t u, v;
            threefry2x32(sub0, sub1, 0u, (uint32_t)tid, u, v);
            rr = x > bits_to_uniform(u ^ v);
        }
        res = rr;
        int c = __syncthreads_count((tid < LN && res) ? 1 : 0);
        float m = (float)c / (float)LN;
        if (fabsf(m - xm) <= tol) break;
    }
    if (tid < LN) {
        float v = res ? 1.0f : 0.0f;
        if (tid == 0 || tid == LN - 1) v = 1.0f;
        d_mask[tid] = v;
    }
}

// ---------------------------------------------------------------------------
// apply: out[0:n4m) = kspace * mask[h] ; out[n4m:n4tot) = mask[h] broadcast.
//    1 float4 / thread (fully coalesced). Zero-mask lines written as zeros
//    WITHOUT loading kspace. (Unchanged from R9 — measured at LTS ceiling.)
// ---------------------------------------------------------------------------
__global__ void __launch_bounds__(256) apply_mask_kernel(
    const float4* __restrict__ ksp, float4* __restrict__ out,
    int n4m, int n4tot) {
    int idx = blockIdx.x * blockDim.x + threadIdx.x;
    if (idx >= n4tot) return;
    if (idx < n4m) {
        int row = idx / 80;            // row of 320 floats (W=320 -> 80 float4)
        float m = d_mask[row % LN];    // exactly 0.0f or 1.0f
        if (m != 0.0f) {
            __stcs(&out[idx], __ldcs(&ksp[idx]));
        } else {
            __stcs(&out[idx], make_float4(0.f, 0.f, 0.f, 0.f));
        }
    } else {
        int row = (idx - n4m) / 80;
        float m = d_mask[row % LN];
        __stcs(&out[idx], make_float4(m, m, m, m));
    }
}

extern "C" void kernel_launch(void* const* d_in, const int* in_sizes, int n_in,
                              void* d_out, int out_size) {
    const float* kspace   = (const float*)d_in[0];  // (256,2,320,320)
    const float* sparsity = (const float*)d_in[1];  // scalar
    const float* logits   = (const float*)d_in[2];  // (320,)

    // Host-side threefry split chain (independent of device inputs).
    // JAX partitionable split: new_key = TF(key,0,0), sub = TF(key,0,1).
    SubKeys subs;
    {
        uint32_t k0 = 0u, k1 = 42u;   // jax.random.key(42)
        for (int i = 0; i < NPROBE; i++) {
            uint32_t s0, s1, n0, n1;
            threefry2x32(k0, k1, 0u, 1u, s0, s1);
            threefry2x32(k0, k1, 0u, 0u, n0, n1);
            subs.s[i] = make_uint2(s0, s1);
            k0 = n0; k1 = n1;
        }
        subs.tail = make_uint2(k0, k1);
    }

    mask_kernel<<<1, 1024>>>(logits, sparsity, subs);

    int n4m   = in_sizes[0] / 4;
    int n4tot = out_size / 4;
    int threads = 256;
    int blocks = (n4tot + threads - 1) / threads;
    apply_mask_kernel<<<blocks, threads>>>(
        (const float4*)kspace, (float4*)d_out, n4m, n4tot);
}

// round 12
// speedup vs baseline: 1.4729x; 1.0183x over previous
#include <cuda_runtime.h>
#include <cstdint>
#include <math.h>

// ---------------------------------------------------------------------------
// LOUPE sampler.
//  Host: threefry split-chain (data-independent) -> 32 candidate sub-keys.
//  mask_kernel : 32 blocks x 320 threads, one candidate each; last-block
//    ticket selects first accepted candidate -> d_mask (seq. fallback).
//    Fires PDL trigger at entry so apply's launch overlaps execution.
//  apply_mask  : PDL secondary; index math before cudaGridDependencySync,
//    then bandwidth phase (AT LTS CEILING — access pattern frozen).
// Output: [masked_kspace 256*2*320*320 f32][mask_full 256*1*320*320 f32]
// ---------------------------------------------------------------------------

#define SLOPE  5.0f
#define LN     320
#define NPROBE 32

struct SubKeys {
    uint2 s[NPROBE];   // sub-key for candidate i
    uint2 tail;        // key state after NPROBE splits (fallback chain)
};

__device__ float    d_mask[LN];
__device__ float    d_xs[LN];
__device__ int      d_cnt[NPROBE];
__device__ uint32_t d_words[NPROBE][10];
__device__ int      d_ticket = 0;     // reset by finalizer each run

// --- threefry2x32, 20 rounds (JAX), host+device ---
__host__ __device__ __forceinline__ uint32_t rotl32(uint32_t v, int d) {
    return (v << d) | (v >> (32 - d));
}

__host__ __device__ __forceinline__ void threefry2x32(
    uint32_t k0, uint32_t k1, uint32_t c0, uint32_t c1,
    uint32_t& o0, uint32_t& o1) {
    uint32_t k2 = k0 ^ k1 ^ 0x1BD11BDAu;
    uint32_t x0 = c0 + k0;
    uint32_t x1 = c1 + k1;
#define TF_ROUND(r) { x0 += x1; x1 = rotl32(x1, (r)); x1 ^= x0; }
    TF_ROUND(13) TF_ROUND(15) TF_ROUND(26) TF_ROUND(6)
    x0 += k1; x1 += k2 + 1u;
    TF_ROUND(17) TF_ROUND(29) TF_ROUND(16) TF_ROUND(24)
    x0 += k2; x1 += k0 + 2u;
    TF_ROUND(13) TF_ROUND(15) TF_ROUND(26) TF_ROUND(6)
    x0 += k0; x1 += k1 + 3u;
    TF_ROUND(17) TF_ROUND(29) TF_ROUND(16) TF_ROUND(24)
    x0 += k1; x1 += k2 + 4u;
    TF_ROUND(13) TF_ROUND(15) TF_ROUND(26) TF_ROUND(6)
    x0 += k2; x1 += k0 + 5u;
#undef TF_ROUND
    o0 = x0; o1 = x1;
}

__device__ __forceinline__ float bits_to_uniform(uint32_t b) {
    return __uint_as_float((b >> 9) | 0x3f800000u) - 1.0f;
}

// ---------------------------------------------------------------------------
// mask_kernel: 32 blocks x 320 threads. Block b evaluates candidate b; the
// last block to finish (atomic ticket) performs selection + emission.
// JAX partitionable threefry: bits(key,j) = x0^x1 of TF(key, 0, j).
// mean(rescaled) == sparsity analytically (validated rel_err 0.0).
// ---------------------------------------------------------------------------
__global__ void __launch_bounds__(LN) mask_kernel(
    const float* __restrict__ logits, const float* __restrict__ sparsity_p,
    SubKeys subs) {
    __shared__ float wsum[10];
    __shared__ float sh_xbar;
    __shared__ int   sh_last, sh_sel;

    // PDL: allow the dependent apply kernel to begin launching now.
    cudaTriggerProgrammaticLaunchCompletion();

    const int tid  = threadIdx.x;
    const int wid  = tid >> 5;
    const int lane = tid & 31;
    const int b    = blockIdx.x;

    const float sparsity = __ldg(sparsity_p);

    float s = 1.0f / (1.0f + expf(-SLOPE * logits[tid]));

    // block reduce: xbar
    float a = s;
    for (int o = 16; o > 0; o >>= 1) a += __shfl_down_sync(0xffffffffu, a, o);
    if (lane == 0) wsum[wid] = a;
    __syncthreads();
    if (wid == 0) {
        float t = (lane < 10) ? wsum[lane] : 0.0f;
        for (int o = 8; o > 0; o >>= 1) t += __shfl_down_sync(0xffffffffu, t, o);
        if (lane == 0) sh_xbar = t / (float)LN;
    }
    __syncthreads();

    // rescale; xm == sparsity analytically
    const float xbar = sh_xbar;
    const float r    = sparsity / xbar;
    const float beta = (1.0f - sparsity) / (1.0f - xbar);
    const float x    = (r <= 1.0f) ? (s * r) : (1.0f - (1.0f - s) * beta);
    if (b == 0) d_xs[tid] = x;                 // for fallback
    const float xm  = sparsity;
    const float tol = 1e-3f + 1e-5f * fabsf(xm);

    // draw candidate b
    const uint2 sub = subs.s[b];
    uint32_t u, v;
    threefry2x32(sub.x, sub.y, 0u, (uint32_t)tid, u, v);
    const int pred = x > bits_to_uniform(u ^ v);

    const uint32_t w = __ballot_sync(0xffffffffu, pred);
    if (lane == 0) d_words[b][wid] = w;

    const int c = __syncthreads_count(pred);
    if (tid == 0) d_cnt[b] = c;

    // ---- last-block ticket: finalizer ----
    if (tid == 0) {
        __threadfence();                       // publish d_words/d_cnt/d_xs
        int t = atomicAdd(&d_ticket, 1);
        sh_last = (t == NPROBE - 1) ? 1 : 0;
        if (sh_last) d_ticket = 0;             // reset for next graph replay
    }
    __syncthreads();
    if (!sh_last) return;

    // selection
    if (tid == 0) {
        int sel = -1;
        for (int i = 0; i < NPROBE; i++) {
            float m = (float)(*(volatile int*)&d_cnt[i]) / (float)LN;
            if (fabsf(m - xm) <= tol) { sel = i; break; }
        }
        sh_sel = sel;
    }
    __syncthreads();
    const int sel = sh_sel;

    float vout;
    if (sel >= 0) {
        uint32_t ww = *(volatile uint32_t*)&d_words[sel][wid];
        vout = ((ww >> lane) & 1u) ? 1.0f : 0.0f;
    } else {
        // fallback (rare): continue sequential split chain from subs.tail
        __shared__ uint32_t key0, key1, sub0, sub1;
        if (tid == 0) { key0 = subs.tail.x; key1 = subs.tail.y; }
        __syncthreads();
        const float xl = *(volatile float*)&d_xs[tid];
        bool res = false;
        for (int iter = 0; iter < 100000; ++iter) {
            if (tid == 0) {   // split(key): new=TF(key,0,0), sub=TF(key,0,1)
                uint32_t nk0, nk1, ns0, ns1;
                threefry2x32(key0, key1, 0u, 0u, nk0, nk1);
                threefry2x32(key0, key1, 0u, 1u, ns0, ns1);
                key0 = nk0; key1 = nk1;
                sub0 = ns0; sub1 = ns1;
            }
            __syncthreads();
            uint32_t uu, vv;
            threefry2x32(sub0, sub1, 0u, (uint32_t)tid, uu, vv);
            res = xl > bits_to_uniform(uu ^ vv);
            int cc = __syncthreads_count(res ? 1 : 0);
            float m = (float)cc / (float)LN;
            if (fabsf(m - xm) <= tol) break;
        }
        vout = res ? 1.0f : 0.0f;
    }

    if (tid == 0 || tid == LN - 1) vout = 1.0f;
    d_mask[tid] = vout;
}

// ---------------------------------------------------------------------------
// apply (PDL secondary): index math first, grid-dependency sync, then the
// bandwidth phase. Access pattern identical to R9 (measured at LTS ceiling).
// ---------------------------------------------------------------------------
__global__ void __launch_bounds__(256) apply_mask_kernel(
    const float4* __restrict__ ksp, float4* __restrict__ out,
    int n4m, int n4tot) {
    const int idx = blockIdx.x * blockDim.x + threadIdx.x;

    // independent prologue (overlaps mask execution)
    const bool in_ksp = idx < n4m;
    const int  row    = in_ksp ? ((idx / 80) % LN)
                               : (((idx - n4m) / 80) % LN);

    // wait for mask_kernel's writes to be visible
    cudaGridDependencySynchronize();

    if (idx >= n4tot) return;
    const float m = d_mask[row];       // exactly 0.0f or 1.0f
    if (in_ksp) {
        if (m != 0.0f) {
            __stcs(&out[idx], __ldcs(&ksp[idx]));
        } else {
            __stcs(&out[idx], make_float4(0.f, 0.f, 0.f, 0.f));
        }
    } else {
        __stcs(&out[idx], make_float4(m, m, m, m));
    }
}

extern "C" void kernel_launch(void* const* d_in, const int* in_sizes, int n_in,
                              void* d_out, int out_size) {
    const float* kspace   = (const float*)d_in[0];  // (256,2,320,320)
    const float* sparsity = (const float*)d_in[1];  // scalar
    const float* logits   = (const float*)d_in[2];  // (320,)

    // Host-side threefry split chain (independent of device inputs).
    // JAX partitionable split: new_key = TF(key,0,0), sub = TF(key,0,1).
    SubKeys subs;
    {
        uint32_t k0 = 0u, k1 = 42u;   // jax.random.key(42)
        for (int i = 0; i < NPROBE; i++) {
            uint32_t s0, s1, n0, n1;
            threefry2x32(k0, k1, 0u, 1u, s0, s1);
            threefry2x32(k0, k1, 0u, 0u, n0, n1);
            subs.s[i] = make_uint2(s0, s1);
            k0 = n0; k1 = n1;
        }
        subs.tail = make_uint2(k0, k1);
    }

    mask_kernel<<<NPROBE, LN>>>(logits, sparsity, subs);

    int n4m   = in_sizes[0] / 4;
    int n4tot = out_size / 4;
    int threads = 256;
    int blocks  = (n4tot + threads - 1) / threads;

    // PDL launch: apply may begin launching as soon as mask triggers.
    cudaLaunchConfig_t cfg = {};
    cfg.gridDim  = dim3((unsigned)blocks, 1, 1);
    cfg.blockDim = dim3((unsigned)threads, 1, 1);
    cfg.dynamicSmemBytes = 0;
    cfg.stream = 0;
    cudaLaunchAttribute attr[1];
    attr[0].id = cudaLaunchAttributeProgrammaticStreamSerialization;
    attr[0].val.programmaticStreamSerializationAllowed = 1;
    cfg.attrs = attr;
    cfg.numAttrs = 1;
    cudaLaunchKernelEx(&cfg, apply_mask_kernel,
                       (const float4*)kspace, (float4*)d_out, n4m, n4tot);
}